// round 16
// baseline (speedup 1.0000x reference)
#include <cuda_runtime.h>
#include <cuda_bf16.h>

// -------------------- scratch (no allocations allowed) --------------------
#define CAP 262144   // >= S*B*N = 204800
#define GBLOCKS 512  // all-resident persistent grid (<= 4 blocks/SM * 128 SMs)

__device__ int      g_pos[CAP];   // pos[inst*N + node_local] = tour position
__device__ int      g_win[CAP];   // packed winner: e | (is_reverse << 30)
__device__ unsigned g_barc[2];    // monotonic grid-barrier tickets (never reset)

#define NOTFOUND 0x7fffffff
#define REVBIT   0x40000000
#define EMASK    0x3fffffff

// -------------------- input identification (uniform) ----------------------
__device__ __forceinline__ bool is64_arange(const unsigned* p) {
    return p[0]==0u && p[1]==0u && p[2]==1u && p[3]==0u &&
           p[4]==2u && p[5]==0u && p[6]==3u && p[7]==0u;
}
__device__ __forceinline__ bool is32_arange(const unsigned* p) {
    return p[0]==0u && p[1]==1u && p[2]==2u && p[3]==3u &&
           p[4]==4u && p[5]==5u && p[6]==6u && p[7]==7u;
}
// bit0 = pb is node_offset (so pa is y), bit1 = ints are 64-bit
__device__ __forceinline__ int detect_cfg(const unsigned* pa, const unsigned* pb) {
    if (is64_arange(pa)) return 2;
    if (is32_arange(pa)) return 0;
    if (is64_arange(pb)) return 3;
    return 1;
}

// fast exact division by N for dividends < 2^32 / N (magic = 2^32/N + 1)
__device__ __forceinline__ unsigned fdiv(unsigned j, unsigned magic) {
    return __umulhi(j, magic);
}

// Monotonic-ticket grid barrier: safe across CUDA-graph replays (no reset).
// All GBLOCKS blocks are co-resident => no deadlock.
__device__ __forceinline__ void grid_barrier(int which) {
    __syncthreads();
    if (threadIdx.x == 0) {
        __threadfence();                       // publish phase writes
        unsigned ticket = atomicAdd(&g_barc[which], 1u);
        unsigned target = ticket - (ticket % gridDim.x) + gridDim.x;
        while (*(volatile unsigned*)&g_barc[which] < target) { }
    }
    __syncthreads();
}

#define HALF_BAR(h) asm volatile("bar.sync %0, %1;" :: "r"((h) + 1), "r"(128) : "memory")

// -------------------- single fused persistent kernel ----------------------
__global__ void __launch_bounds__(256, 4)
fused_kernel(const unsigned* __restrict__ pa,
             const unsigned* __restrict__ pb,
             const void* __restrict__ eidx,
             const float* __restrict__ emb,
             float* __restrict__ out,
             int total, int E, int instTotal, int N, int EM, unsigned magic) {
    __shared__ int   sidx[2][128];
    __shared__ float sacc[2][4 * 128];

    int cfg = detect_cfg(pa, pb);
    const int* y = (const int*)((cfg & 1) ? pa : pb);
    int t = threadIdx.x;
    int gtid = blockIdx.x * blockDim.x + t;
    int gstride = gridDim.x * blockDim.x;

    // ---- phase 1: inverse permutation + winner init ----
    for (int j = gtid; j < total; j += gstride) {
        unsigned inst = fdiv((unsigned)j, magic);
        int i = j - (int)inst * N;
        g_pos[(int)inst * N + y[j]] = i;
        g_win[j] = NOTFOUND;
    }
    grid_barrier(0);

    // ---- phase 2: scatter edges onto tour positions ----
    unsigned uN = (unsigned)N;
    for (int e = gtid; e < E; e += gstride) {
        unsigned s, d;
        if (cfg & 2) {
            const long long* p = (const long long*)eidx;
            s = (unsigned)p[e]; d = (unsigned)p[e + E];
        } else {
            const int* p = (const int*)eidx;
            s = (unsigned)p[e]; d = (unsigned)p[e + E];
        }
        unsigned is = fdiv(s, magic);
        unsigned id = fdiv(d, magic);
        if (is != id) continue;                 // cross-instance: can't match
        unsigned sl = s - is * uN;
        unsigned dl = d - id * uN;
        int base = (int)is * N;
        int ps = __ldcg(&g_pos[base + sl]);
        int pd = __ldcg(&g_pos[base + dl]);
        int psn = (ps + 1 == N) ? 0 : ps + 1;
        int pdn = (pd + 1 == N) ? 0 : pd + 1;
        if (psn == pd) atomicMin(&g_win[base + ps], e);           // forward
        if (pdn == ps) atomicMin(&g_win[base + pd], e | REVBIT);  // reverse
    }
    grid_barrier(1);

    // ---- phase 3: gather + mean (two independent 128-thread halves) ----
    int h    = t >> 7;        // half id: 0 or 1
    int t128 = t & 127;       // thread id within half
    int w = t128 >> 5, l = t128 & 31;

    for (int pi = blockIdx.x; pi * 2 < instTotal; pi += gridDim.x) {
        int inst = pi * 2 + h;
        if (inst < instTotal) {
            int base = inst * N;
            if (t128 < N) {
                int v = __ldcg(&g_win[base + t128]);
                sidx[h][t128] = (v == NOTFOUND) ? -1 : (v & EMASK);
            }
            HALF_BAR(h);

            if (EM == 128) {
                float4 acc = make_float4(0.f, 0.f, 0.f, 0.f);
                #pragma unroll 8
                for (int i = w; i < N; i += 4) {
                    int v = sidx[h][i];
                    if (v >= 0) {
                        float4 x = ((const float4*)(emb + (long long)v * 128))[l];
                        acc.x += x.x; acc.y += x.y; acc.z += x.z; acc.w += x.w;
                    }
                }
                ((float4*)(sacc[h] + w * 128))[l] = acc;
                HALF_BAR(h);
                float s = sacc[h][t128] + sacc[h][128 + t128] +
                          sacc[h][256 + t128] + sacc[h][384 + t128];
                out[(long long)inst * 128 + t128] = s * (1.0f / (float)N);
            } else {
                if (t128 < EM) {
                    float acc = 0.0f;
                    for (int i = 0; i < N; i++) {
                        int v = sidx[h][i];
                        if (v >= 0) acc += emb[(long long)v * EM + t128];
                    }
                    out[(long long)inst * EM + t128] = acc * (1.0f / (float)N);
                }
                HALF_BAR(h);
            }
        }
    }
}

// -------------------- launcher --------------------------------------------
extern "C" void kernel_launch(void* const* d_in, const int* in_sizes, int n_in,
                              void* d_out, int out_size) {
    // Identify inputs by element count (robust to ordering):
    //   edge_emb -> largest, edge_index -> second, y/node_offset -> the pair.
    int order[16];
    for (int i = 0; i < n_in && i < 16; i++) order[i] = i;
    for (int i = 0; i < n_in; i++)
        for (int j = i + 1; j < n_in; j++)
            if (in_sizes[order[j]] > in_sizes[order[i]]) {
                int tmp = order[i]; order[i] = order[j]; order[j] = tmp;
            }
    int emb_i  = order[0];
    int eidx_i = order[1];
    int pa_i   = order[2];
    int pb_i   = order[3];

    const float*    emb  = (const float*)d_in[emb_i];
    const void*     eidx = d_in[eidx_i];
    const unsigned* pa   = (const unsigned*)d_in[pa_i];
    const unsigned* pb   = (const unsigned*)d_in[pb_i];
    float*          out  = (float*)d_out;

    int total = in_sizes[pa_i];                    // S*B*N
    int E  = in_sizes[eidx_i] / 2;
    int EM = in_sizes[emb_i] / E;                  // 128
    int inst = out_size / EM;                      // S*B
    int N = total / inst;                          // 100

    unsigned magic = (unsigned)(0x100000000ULL / (unsigned)N + 1ULL);

    fused_kernel<<<GBLOCKS, 256>>>(pa, pb, eidx, emb, out,
                                   total, E, inst, N, EM, magic);
}